// round 15
// baseline (speedup 1.0000x reference)
#include <cuda_runtime.h>

#define TPB  256
#define NBT  32
#define PSTR 33
#define NP   65
#define LAM3  1e-4f
#define RIDGE 1e-4f

__device__ __host__ constexpr float C0f(int a) {
    return (a == 1) ? 10.f : (a == 2) ? 19.f :
           (a <= 61) ? 20.f : (a == 62) ? 19.f : (a == 63) ? 10.f : 1.f;
}
__device__ __host__ constexpr float C1f(int a) {
    return (a == 1) ? -12.f : (a <= 61) ? -15.f :
           (a == 62) ? -12.f : (a == 63) ? -3.f : 0.f;
}
__device__ __host__ constexpr float C2f(int a) {
    return (a <= 61) ? 6.f : (a == 62) ? 3.f : 0.f;
}
__device__ __host__ constexpr float C3f(int a) {
    return (a <= 61) ? -1.f : 0.f;
}
__device__ __host__ constexpr float diagf(int p) {
    return ((p < 63) ? 2.f : 1.f) + LAM3 * C0f(p + 1) + RIDGE;
}

#define FSOLVE(i0v,l10v,l20v,i1v,l21v,i2v, b0v,b1v,b2v, w0v,w1v,w2v) \
    w0v = (b0v) * (i0v); \
    w1v = ((b1v) - w0v * (l10v)) * (i1v); \
    w2v = ((b2v) - w0v * (l20v) - w1v * (l21v)) * (i2v);
#define BSOLVE(i0v,l10v,l20v,i1v,l21v,i2v, b0v,b1v,b2v, w0v,w1v,w2v) \
    w2v = (b2v) * (i2v); \
    w1v = ((b1v) - (l21v) * w2v) * (i1v); \
    w0v = ((b0v) - (l10v) * w1v - (l20v) * w2v) * (i0v);

// smem float offsets
#define O_STH  6144        // 65*33 (aliased as sou)
#define O_SGX  8289        // 64*33 (aliased as sgl after phase1)
#define O_SGY  10401       // 64*33
#define O_SGR  12513       // 7*3*3*32
#define O_SXC  14529       // 264*32
#define SMEM_FLOATS 22977
#define SMEM_BYTES  (SMEM_FLOATS*4)
#define SXF(i) sxc[(i)*32 + col]

// role geometry (constexpr)
template<int ROLE> struct Geo {
    static constexpr int  s    = (ROLE < 5 && !(ROLE & 1)) ? 6 : 5;
    static constexpr int  hp0  = (ROLE + 1) >> 1;
    static constexpr int  hp   = (hp0 > 3) ? 3 : hp0;
    static constexpr int  o    = ROLE * 8 + hp;
    static constexpr bool hasL = (ROLE > 0);
    static constexpr bool hasR = (ROLE < 7);
    static constexpr int  ec   = hasR ? (s + 3) : s;
};

struct P1 { float e[9]; float r[9]; };

template<int ROLE>
__device__ __forceinline__ P1 phase1(const float* __restrict__ sth,
                                     const float* __restrict__ sgx,
                                     const float* __restrict__ sgy,
                                     int col, float v0v)
{
    using G = Geo<ROLE>;
    P1 p;
    float thp = sth[G::o * PSTR + col];
    float sp, cp; __sincosf(thp, &sp, &cp);
    float gxp = sgx[G::o * PSTR + col], gyp = sgy[G::o * PSTR + col];
    #pragma unroll
    for (int i = 1; i <= 9; ++i) {
        if (i <= G::ec) {
            const int k = G::o + i;
            float th = sth[k * PSTR + col];
            float sv, cv; __sincosf(th, &sv, &cv);
            float gx = 0.f, gy = 0.f;
            if (k < 64) { gx = sgx[k * PSTR + col]; gy = sgy[k * PSTR + col]; }
            p.e[i - 1] = cp * cv + sp * sv;
            p.r[i - 1] = cv * (gxp + gx) + sv * (gyp + gy);
            cp = cv; sp = sv; gxp = gx; gyp = gy;
        } else { p.e[i - 1] = 0.f; p.r[i - 1] = 0.f; }
    }
    if (ROLE == 0) {
        p.r[0] -= (p.e[0] - 3.f * LAM3) * v0v;
        p.r[1] -= 3.f * LAM3 * v0v;
        p.r[2] += LAM3 * v0v;
    }
    return p;
}

template<int ROLE>
__device__ __forceinline__ void phase2(const P1& p,
                                       float4* __restrict__ s4,
                                       float* __restrict__ sgl,
                                       float* __restrict__ sgr,
                                       float* __restrict__ sxc,
                                       int col)
{
    using G = Geo<ROLE>;
    constexpr int s = G::s, o = G::o;

    constexpr float aL0x = G::hasL ? LAM3 * C3f(o - 2) : 0.f;
    constexpr float aL0y = G::hasL ? LAM3 * C2f(o - 1) : 0.f;
    constexpr float aL1y = G::hasL ? LAM3 * C3f(o - 1) : 0.f;
    constexpr float aL1z = G::hasL ? LAM3 * C2f(o)     : 0.f;
    constexpr float aL2z = G::hasL ? LAM3 * C3f(o)     : 0.f;
    const float aL0z = G::hasL ? (p.e[0] + LAM3 * C1f(o)) : 0.f;
    constexpr int  Je   = o + s - 1;
    constexpr float aR0x = G::hasR ? LAM3 * C3f(Je - 1) : 0.f;
    constexpr float aR1x = G::hasR ? LAM3 * C2f(Je)     : 0.f;
    constexpr float aR1y = G::hasR ? LAM3 * C3f(Je)     : 0.f;
    constexpr float aR2y = G::hasR ? LAM3 * C2f(Je + 1) : 0.f;
    constexpr float aR2z = G::hasR ? LAM3 * C3f(Je + 1) : 0.f;
    const float aR2x = G::hasR ? (p.e[s] + LAM3 * C1f(Je + 1)) : 0.f;

    float L1p=0.f, L2p1=0.f, L2p2=0.f, L3p1=0.f, L3p2=0.f, L3p3=0.f;
    float zp1=0.f, zp2=0.f, zp3=0.f;
    float gl1x=0,gl1y=0,gl1z=0, gl2x=0,gl2y=0,gl2z=0, gl3x=0,gl3y=0,gl3z=0;
    float gr1x=0,gr1y=0,gr1z=0, gr2x=0,gr2y=0,gr2z=0, gr3x=0,gr3y=0,gr3z=0;
    float sl00=0,sl01=0,sl02=0,sl11=0,sl12=0,sl22=0;
    float sr00=0,sr01=0,sr02=0,sr11=0,sr12=0,sr22=0;
    float sx00=0,sx01=0,sx02=0,sx10=0,sx11=0,sx12=0,sx20=0,sx21=0,sx22=0;
    float rl0=0,rl1=0,rl2=0, rr0=0,rr1=0,rr2=0;

    #pragma unroll
    for (int jj = 0; jj < s; ++jj) {
        const int j = o + jj;
        float d   = diagf(j) - L1p*L1p - L2p2*L2p2 - L3p3*L3p3;
        float inv = rsqrtf(d);
        float s1v = (jj < s - 1)
                  ? (p.e[jj + 1] + LAM3 * C1f(j + 1) - L2p1*L1p - L3p2*L2p2) : 0.f;
        float s2v = (jj < s - 2) ? (LAM3 * C2f(j + 1) - L3p1*L1p) : 0.f;
        float s3v = (jj < s - 3) ? (LAM3 * C3f(j + 1)) : 0.f;
        float L1 = s1v * inv, L2 = s2v * inv, L3 = s3v * inv;
        float z  = (p.r[jj] - L1p*zp1 - L2p2*zp2 - L3p3*zp3) * inv;

        float4 pk;
        pk.x = L1 * inv; pk.y = L2 * inv; pk.z = L3 * inv; pk.w = z * inv;
        s4[(ROLE * 6 + jj) * 32 + col] = pk;

        float glx=0.f, gly=0.f, glz=0.f;
        if (G::hasL) {
            float ax = (jj == 0) ? aL0x : 0.f;
            float ay = (jj == 0) ? aL0y : (jj == 1) ? aL1y : 0.f;
            float az = (jj == 0) ? aL0z : (jj == 1) ? aL1z : (jj == 2) ? aL2z : 0.f;
            glx = (ax - L1p*gl1x - L2p2*gl2x - L3p3*gl3x) * inv;
            gly = (ay - L1p*gl1y - L2p2*gl2y - L3p3*gl3y) * inv;
            glz = (az - L1p*gl1z - L2p2*gl2z - L3p3*gl3z) * inv;
            sl00 += glx*glx; sl01 += glx*gly; sl02 += glx*glz;
            sl11 += gly*gly; sl12 += gly*glz; sl22 += glz*glz;
            rl0 += glx*z; rl1 += gly*z; rl2 += glz*z;
            const int gb = (((ROLE - 1) * 6 + jj) * 3) * 32 + col;
            sgl[gb]      = glx * inv;
            sgl[gb + 32] = gly * inv;
            sgl[gb + 64] = glz * inv;
        }
        if (G::hasR && jj >= s - 3) {
            const int rstep = jj - (s - 3);
            float ax = (rstep == 0) ? aR0x : (rstep == 1) ? aR1x : aR2x;
            float ay = (rstep == 1) ? aR1y : (rstep == 2) ? aR2y : 0.f;
            float az = (rstep == 2) ? aR2z : 0.f;
            float grx = (ax - L1p*gr1x - L2p2*gr2x - L3p3*gr3x) * inv;
            float gry = (ay - L1p*gr1y - L2p2*gr2y - L3p3*gr3y) * inv;
            float grz = (az - L1p*gr1z - L2p2*gr2z - L3p3*gr3z) * inv;
            sr00 += grx*grx; sr01 += grx*gry; sr02 += grx*grz;
            sr11 += gry*gry; sr12 += gry*grz; sr22 += grz*grz;
            rr0 += grx*z; rr1 += gry*z; rr2 += grz*z;
            if (G::hasL) {
                sx00 += glx*grx; sx01 += glx*gry; sx02 += glx*grz;
                sx10 += gly*grx; sx11 += gly*gry; sx12 += gly*grz;
                sx20 += glz*grx; sx21 += glz*gry; sx22 += glz*grz;
            }
            const int gb = ((ROLE * 3 + rstep) * 3) * 32 + col;
            sgr[gb]      = grx * inv;
            sgr[gb + 32] = gry * inv;
            sgr[gb + 64] = grz * inv;
            gr3x=gr2x; gr3y=gr2y; gr3z=gr2z;
            gr2x=gr1x; gr2y=gr1y; gr2z=gr1z;
            gr1x=grx;  gr1y=gry;  gr1z=grz;
        }
        if (G::hasL) {
            gl3x=gl2x; gl3y=gl2y; gl3z=gl2z;
            gl2x=gl1x; gl2y=gl1y; gl2z=gl1z;
            gl1x=glx;  gl1y=gly;  gl1z=glz;
        }
        L3p3=L3p2; L3p2=L3p1; L3p1=L3;
        L2p2=L2p1; L2p1=L2; L1p=L1;
        zp3=zp2; zp2=zp1; zp1=z;
    }

    // exchange
    if (G::hasL) {
        const int bsl = (ROLE - 1) * 6;
        SXF(bsl+0)=sl00; SXF(bsl+1)=sl01; SXF(bsl+2)=sl02;
        SXF(bsl+3)=sl11; SXF(bsl+4)=sl12; SXF(bsl+5)=sl22;
        const int brl = 138 + (ROLE - 1) * 3;
        SXF(brl+0)=rl0; SXF(brl+1)=rl1; SXF(brl+2)=rl2;
    }
    if (G::hasR) {
        const int bsr = 42 + ROLE * 6;
        SXF(bsr+0)=sr00; SXF(bsr+1)=sr01; SXF(bsr+2)=sr02;
        SXF(bsr+3)=sr11; SXF(bsr+4)=sr12; SXF(bsr+5)=sr22;
        const int brr = 159 + ROLE * 3;
        SXF(brr+0)=rr0; SXF(brr+1)=rr1; SXF(brr+2)=rr2;
        constexpr int q = o + s;
        const int bdd = 180 + ROLE * 6;
        SXF(bdd+0) = diagf(q);
        SXF(bdd+1) = p.e[s + 1] + LAM3 * C1f(q + 1);
        SXF(bdd+2) = LAM3 * C2f(q + 1);
        SXF(bdd+3) = diagf(q + 1);
        SXF(bdd+4) = p.e[s + 2] + LAM3 * C1f(q + 2);
        SXF(bdd+5) = diagf(q + 2);
        const int brq = 222 + ROLE * 3;
        SXF(brq+0)=p.r[s]; SXF(brq+1)=p.r[s+1]; SXF(brq+2)=p.r[s+2];
    }
    if (G::hasL && G::hasR) {   // cross-term block (bug in R14: was missing)
        const int bcr = 84 + (ROLE - 1) * 9;
        SXF(bcr+0)=sx00; SXF(bcr+1)=sx01; SXF(bcr+2)=sx02;
        SXF(bcr+3)=sx10; SXF(bcr+4)=sx11; SXF(bcr+5)=sx12;
        SXF(bcr+6)=sx20; SXF(bcr+7)=sx21; SXF(bcr+8)=sx22;
    }
}

template<int ROLE>
__device__ __forceinline__ void backsub(const float4* __restrict__ s4,
                                        const float* __restrict__ sgl,
                                        const float* __restrict__ sgr,
                                        const float* __restrict__ sxc,
                                        float* __restrict__ sou,
                                        int col, float v0v)
{
    using G = Geo<ROLE>;
    constexpr int s = G::s, o = G::o;

    float xL0=0,xL1=0,xL2=0, xR0=0,xR1=0,xR2=0;
    if (G::hasL) {
        const int xb = 243 + (ROLE - 1) * 3;
        xL0 = SXF(xb+0); xL1 = SXF(xb+1); xL2 = SXF(xb+2);
    }
    if (G::hasR) {
        const int xb = 243 + ROLE * 3;
        xR0 = SXF(xb+0); xR1 = SXF(xb+1); xR2 = SXF(xb+2);
    }

    float y1 = G::hasR ? xR0 : 0.f;
    float y2 = G::hasR ? xR1 : 0.f;
    float y3 = G::hasR ? xR2 : 0.f;
    #pragma unroll
    for (int jj = s - 1; jj >= 0; --jj) {
        float4 pk = s4[(ROLE * 6 + jj) * 32 + col];
        float w = pk.w;
        if (G::hasL) {
            const int gb = (((ROLE - 1) * 6 + jj) * 3) * 32 + col;
            w -= sgl[gb] * xL0 + sgl[gb + 32] * xL1 + sgl[gb + 64] * xL2;
        }
        if (G::hasR && jj >= s - 3) {
            const int gb = ((ROLE * 3 + (jj - (s - 3))) * 3) * 32 + col;
            w -= sgr[gb] * xR0 + sgr[gb + 32] * xR1 + sgr[gb + 64] * xR2;
        }
        float x = w - pk.x * y1 - pk.y * y2 - pk.z * y3;
        sou[(o + jj + 1) * PSTR + col] = x;
        y3 = y2; y2 = y1; y1 = x;
    }
    if (ROLE == 0) sou[col] = v0v;
    if (G::hasR) {
        constexpr int q = o + s;
        sou[(q + 1) * PSTR + col] = xR0;
        sou[(q + 2) * PSTR + col] = xR1;
        sou[(q + 3) * PSTR + col] = xR2;
    }
}

__global__ __launch_bounds__(TPB, 2) void AlpamayoR1_solve_kernel(
    const float* __restrict__ dxy,
    const float* __restrict__ theta,
    const float* __restrict__ v0,
    float* __restrict__ out, int B)
{
    extern __shared__ float4 smem4[];
    float4* s4  = smem4;
    float*  sm  = (float*)smem4;
    float*  sth = sm + O_STH;
    float*  sgx = sm + O_SGX;
    float*  sgy = sm + O_SGY;
    float*  sgl = sm + O_SGX;            // alias (safe after phase-1 sync)
    float*  sgr = sm + O_SGR;
    float*  sxc = sm + O_SXC;
    float*  sou = sth;                   // alias (safe after phase-1 sync)

    const int t    = threadIdx.x;
    const int role = t >> 5;
    const int col  = t & 31;
    const int b0   = blockIdx.x * NBT;

    // ---- staging ----
    {
        const float4* th4 = (const float4*)(theta + (size_t)b0 * NP);
        for (int i = t; i < (NBT * NP) / 4; i += TPB) {
            float4 v = th4[i];
            int f = 4 * i;
            int bl0 = f / NP, k0 = f - bl0 * NP;               sth[k0 * PSTR + bl0] = v.x;
            int f1 = f + 1, bl1 = f1 / NP, k1 = f1 - bl1 * NP; sth[k1 * PSTR + bl1] = v.y;
            int f2 = f + 2, bl2 = f2 / NP, k2 = f2 - bl2 * NP; sth[k2 * PSTR + bl2] = v.z;
            int f3 = f + 3, bl3 = f3 / NP, k3 = f3 - bl3 * NP; sth[k3 * PSTR + bl3] = v.w;
        }
        const float4* dx4 = (const float4*)(dxy + (size_t)b0 * 128);
        #pragma unroll 4
        for (int i = t; i < NBT * 32; i += TPB) {
            float4 v = dx4[i];
            int bl = i >> 5, s0 = (i & 31) * 2;
            sgx[s0 * PSTR + bl]       = 2.f * v.x;
            sgy[s0 * PSTR + bl]       = 2.f * v.y;
            sgx[(s0 + 1) * PSTR + bl] = 2.f * v.z;
            sgy[(s0 + 1) * PSTR + bl] = 2.f * v.w;
        }
    }
    float v0v = (role == 0) ? v0[b0 + col] : 0.f;
    __syncthreads();

    // ---- phase 1 (role-specialized, warp-uniform dispatch) ----
    P1 p;
    switch (role) {
        case 0: p = phase1<0>(sth, sgx, sgy, col, v0v); break;
        case 1: p = phase1<1>(sth, sgx, sgy, col, v0v); break;
        case 2: p = phase1<2>(sth, sgx, sgy, col, v0v); break;
        case 3: p = phase1<3>(sth, sgx, sgy, col, v0v); break;
        case 4: p = phase1<4>(sth, sgx, sgy, col, v0v); break;
        case 5: p = phase1<5>(sth, sgx, sgy, col, v0v); break;
        case 6: p = phase1<6>(sth, sgx, sgy, col, v0v); break;
        default: p = phase1<7>(sth, sgx, sgy, col, v0v); break;
    }
    __syncthreads();   // sgx/sgy reads done -> sgl alias safe

    // ---- phase 2 ----
    switch (role) {
        case 0: phase2<0>(p, s4, sgl, sgr, sxc, col); break;
        case 1: phase2<1>(p, s4, sgl, sgr, sxc, col); break;
        case 2: phase2<2>(p, s4, sgl, sgr, sxc, col); break;
        case 3: phase2<3>(p, s4, sgl, sgr, sxc, col); break;
        case 4: phase2<4>(p, s4, sgl, sgr, sxc, col); break;
        case 5: phase2<5>(p, s4, sgl, sgr, sxc, col); break;
        case 6: phase2<6>(p, s4, sgl, sgr, sxc, col); break;
        default: phase2<7>(p, s4, sgl, sgr, sxc, col); break;
    }
    __syncthreads();

    // ---- interface: 7-block (3x3) block-tridiagonal solve, warp 0 only ----
    if (role == 0) {
        float fi0[7],fl10[7],fl20[7],fi1[7],fl21[7],fi2[7];
        float fu0[7],fu1[7],fu2[7];
        float W00a[7],W01a[7],W02a[7],W10a[7],W11a[7],W12a[7],W20a[7],W21a[7],W22a[7];
        #pragma unroll
        for (int i = 0; i < 7; ++i) {
            float D00 = SXF(180+i*6+0) - SXF(42+i*6+0) - SXF(i*6+0);
            float D10 = SXF(180+i*6+1) - SXF(42+i*6+1) - SXF(i*6+1);
            float D20 = SXF(180+i*6+2) - SXF(42+i*6+2) - SXF(i*6+2);
            float D11 = SXF(180+i*6+3) - SXF(42+i*6+3) - SXF(i*6+3);
            float D21 = SXF(180+i*6+4) - SXF(42+i*6+4) - SXF(i*6+4);
            float D22 = SXF(180+i*6+5) - SXF(42+i*6+5) - SXF(i*6+5);
            float t0  = SXF(222+i*3+0) - SXF(159+i*3+0) - SXF(138+i*3+0);
            float t1  = SXF(222+i*3+1) - SXF(159+i*3+1) - SXF(138+i*3+1);
            float t2  = SXF(222+i*3+2) - SXF(159+i*3+2) - SXF(138+i*3+2);
            if (i > 0) {
                int cb = 84 + (i - 1) * 9;
                float B00=-SXF(cb+0), B01=-SXF(cb+3), B02=-SXF(cb+6);
                float B10=-SXF(cb+1), B11=-SXF(cb+4), B12=-SXF(cb+7);
                float B20=-SXF(cb+2), B21=-SXF(cb+5), B22=-SXF(cb+8);
                FSOLVE(fi0[i-1],fl10[i-1],fl20[i-1],fi1[i-1],fl21[i-1],fi2[i-1],
                       B00,B01,B02, W00a[i],W01a[i],W02a[i])
                FSOLVE(fi0[i-1],fl10[i-1],fl20[i-1],fi1[i-1],fl21[i-1],fi2[i-1],
                       B10,B11,B12, W10a[i],W11a[i],W12a[i])
                FSOLVE(fi0[i-1],fl10[i-1],fl20[i-1],fi1[i-1],fl21[i-1],fi2[i-1],
                       B20,B21,B22, W20a[i],W21a[i],W22a[i])
                D00 -= W00a[i]*W00a[i] + W01a[i]*W01a[i] + W02a[i]*W02a[i];
                D10 -= W10a[i]*W00a[i] + W11a[i]*W01a[i] + W12a[i]*W02a[i];
                D20 -= W20a[i]*W00a[i] + W21a[i]*W01a[i] + W22a[i]*W02a[i];
                D11 -= W10a[i]*W10a[i] + W11a[i]*W11a[i] + W12a[i]*W12a[i];
                D21 -= W20a[i]*W10a[i] + W21a[i]*W11a[i] + W22a[i]*W12a[i];
                D22 -= W20a[i]*W20a[i] + W21a[i]*W21a[i] + W22a[i]*W22a[i];
                t0  -= W00a[i]*fu0[i-1] + W01a[i]*fu1[i-1] + W02a[i]*fu2[i-1];
                t1  -= W10a[i]*fu0[i-1] + W11a[i]*fu1[i-1] + W12a[i]*fu2[i-1];
                t2  -= W20a[i]*fu0[i-1] + W21a[i]*fu1[i-1] + W22a[i]*fu2[i-1];
            }
            fi0[i]  = rsqrtf(D00);
            fl10[i] = D10 * fi0[i];
            fl20[i] = D20 * fi0[i];
            fi1[i]  = rsqrtf(D11 - fl10[i]*fl10[i]);
            fl21[i] = (D21 - fl20[i]*fl10[i]) * fi1[i];
            fi2[i]  = rsqrtf(D22 - fl20[i]*fl20[i] - fl21[i]*fl21[i]);
            FSOLVE(fi0[i],fl10[i],fl20[i],fi1[i],fl21[i],fi2[i],
                   t0,t1,t2, fu0[i],fu1[i],fu2[i])
        }
        float xc0=0.f, xc1=0.f, xc2=0.f;
        #pragma unroll
        for (int i = 6; i >= 0; --i) {
            float t0 = fu0[i], t1 = fu1[i], t2 = fu2[i];
            if (i < 6) {
                t0 -= W00a[i+1]*xc0 + W10a[i+1]*xc1 + W20a[i+1]*xc2;
                t1 -= W01a[i+1]*xc0 + W11a[i+1]*xc1 + W21a[i+1]*xc2;
                t2 -= W02a[i+1]*xc0 + W12a[i+1]*xc1 + W22a[i+1]*xc2;
            }
            float x0, x1, x2;
            BSOLVE(fi0[i],fl10[i],fl20[i],fi1[i],fl21[i],fi2[i], t0,t1,t2, x0,x1,x2)
            SXF(243+i*3+0) = x0; SXF(243+i*3+1) = x1; SXF(243+i*3+2) = x2;
            xc0 = x0; xc1 = x1; xc2 = x2;
        }
    }
    __syncthreads();

    // ---- back substitution ----
    switch (role) {
        case 0: backsub<0>(s4, sgl, sgr, sxc, sou, col, v0v); break;
        case 1: backsub<1>(s4, sgl, sgr, sxc, sou, col, v0v); break;
        case 2: backsub<2>(s4, sgl, sgr, sxc, sou, col, v0v); break;
        case 3: backsub<3>(s4, sgl, sgr, sxc, sou, col, v0v); break;
        case 4: backsub<4>(s4, sgl, sgr, sxc, sou, col, v0v); break;
        case 5: backsub<5>(s4, sgl, sgr, sxc, sou, col, v0v); break;
        case 6: backsub<6>(s4, sgl, sgr, sxc, sou, col, v0v); break;
        default: backsub<7>(s4, sgl, sgr, sxc, sou, col, v0v); break;
    }
    __syncthreads();

    // ---- coalesced float4 store ----
    {
        float4* out4 = (float4*)(out + (size_t)b0 * NP);
        for (int i = t; i < (NBT * NP) / 4; i += TPB) {
            int f = 4 * i;
            int bl0 = f / NP, k0 = f - bl0 * NP;
            int f1 = f + 1, bl1 = f1 / NP, k1 = f1 - bl1 * NP;
            int f2 = f + 2, bl2 = f2 / NP, k2 = f2 - bl2 * NP;
            int f3 = f + 3, bl3 = f3 / NP, k3 = f3 - bl3 * NP;
            float4 v;
            v.x = sou[k0 * PSTR + bl0];
            v.y = sou[k1 * PSTR + bl1];
            v.z = sou[k2 * PSTR + bl2];
            v.w = sou[k3 * PSTR + bl3];
            out4[i] = v;
        }
    }
}

extern "C" void kernel_launch(void* const* d_in, const int* in_sizes, int n_in,
                              void* d_out, int out_size) {
    const float* dxy   = (const float*)d_in[0];
    const float* theta = (const float*)d_in[1];
    const float* v0    = (const float*)d_in[2];
    float* out = (float*)d_out;
    int B = in_sizes[2];

    cudaFuncSetAttribute(AlpamayoR1_solve_kernel,
                         cudaFuncAttributeMaxDynamicSharedMemorySize, SMEM_BYTES);
    int grid = (B + NBT - 1) / NBT;
    AlpamayoR1_solve_kernel<<<grid, TPB, SMEM_BYTES>>>(dxy, theta, v0, out, B);
}

// round 16
// speedup vs baseline: 1.2165x; 1.2165x over previous
#include <cuda_runtime.h>

#define TPB  256
#define NBT  32
#define PSTR 33
#define NP   65
#define LAM3  1e-4f
#define RIDGE 1e-4f

__device__ __forceinline__ float C0f(int a) {
    return (a == 1) ? 10.f : (a == 2) ? 19.f :
           (a <= 61) ? 20.f : (a == 62) ? 19.f : (a == 63) ? 10.f : 1.f;
}
__device__ __forceinline__ float C1f(int a) {
    return (a == 1) ? -12.f : (a <= 61) ? -15.f :
           (a == 62) ? -12.f : (a == 63) ? -3.f : 0.f;
}
__device__ __forceinline__ float C2f(int a) {
    return (a <= 61) ? 6.f : (a == 62) ? 3.f : 0.f;
}
__device__ __forceinline__ float C3f(int a) {
    return (a <= 61) ? -1.f : 0.f;
}
__device__ __forceinline__ float diagf(int p) {
    return ((p < 63) ? 2.f : 1.f) + LAM3 * C0f(p + 1) + RIDGE;
}

#define FSOLVE(i0v,l10v,l20v,i1v,l21v,i2v, b0v,b1v,b2v, w0v,w1v,w2v) \
    w0v = (b0v) * (i0v); \
    w1v = ((b1v) - w0v * (l10v)) * (i1v); \
    w2v = ((b2v) - w0v * (l20v) - w1v * (l21v)) * (i2v);
#define BSOLVE(i0v,l10v,l20v,i1v,l21v,i2v, b0v,b1v,b2v, w0v,w1v,w2v) \
    w2v = (b2v) * (i2v); \
    w1v = ((b1v) - (l21v) * w2v) * (i1v); \
    w0v = ((b0v) - (l10v) * w1v - (l20v) * w2v) * (i0v);

// smem float offsets
#define O_STH  6144        // 65*33 (aliased as sou)
#define O_SGX  8289        // 64*33 (aliased as sgl after phase1)
#define O_SGY  10401       // 64*33
#define O_SGR  12513       // 7*3*3*32
#define O_SXC  14529       // 264*32
#define O_SCB  22980       // 64 float4 band table (16B aligned: 22980*4 % 16 == 0)
#define SMEM_FLOATS 23236
#define SMEM_BYTES  (SMEM_FLOATS*4)
#define SXF(i) sxc[(i)*32 + col]

__global__ __launch_bounds__(TPB, 2) void AlpamayoR1_solve_kernel(
    const float* __restrict__ dxy,
    const float* __restrict__ theta,
    const float* __restrict__ v0,
    float* __restrict__ out, int B)
{
    extern __shared__ float4 smem4[];
    float4* s4  = smem4;                 // 48 rows * 32 float4
    float*  sm  = (float*)smem4;
    float*  sth = sm + O_STH;
    float*  sgx = sm + O_SGX;
    float*  sgy = sm + O_SGY;
    float*  sgl = sm + O_SGX;            // alias (valid after phase-1 sync)
    float*  sgr = sm + O_SGR;
    float*  sxc = sm + O_SXC;
    float4* sCb = (float4*)(sm + O_SCB); // band constants per column j=0..63
    float*  sou = sth;                   // alias (valid after phase-1 sync)

    const int t    = threadIdx.x;
    const int role = t >> 5;             // 0..7, one warp per role
    const int col  = t & 31;             // batch within CTA
    const int b0   = blockIdx.x * NBT;

    // ---- band-constant table: sCb[j] = (diag(j), L*C1(j+1), L*C2(j+1), L*C3(j+1)) ----
    if (t < 64) {
        sCb[t] = make_float4(diagf(t), LAM3 * C1f(t + 1),
                             LAM3 * C2f(t + 1), LAM3 * C3f(t + 1));
    }

    // ---- staging: coalesced float4 loads, transpose into padded shared ----
    {
        const float4* th4 = (const float4*)(theta + (size_t)b0 * NP);
        for (int i = t; i < (NBT * NP) / 4; i += TPB) {      // 520
            float4 v = th4[i];
            int f = 4 * i;
            int bl0 = f / NP, k0 = f - bl0 * NP;             sth[k0 * PSTR + bl0] = v.x;
            int f1 = f + 1, bl1 = f1 / NP, k1 = f1 - bl1 * NP; sth[k1 * PSTR + bl1] = v.y;
            int f2 = f + 2, bl2 = f2 / NP, k2 = f2 - bl2 * NP; sth[k2 * PSTR + bl2] = v.z;
            int f3 = f + 3, bl3 = f3 / NP, k3 = f3 - bl3 * NP; sth[k3 * PSTR + bl3] = v.w;
        }
        const float4* dx4 = (const float4*)(dxy + (size_t)b0 * 128);
        #pragma unroll 4
        for (int i = t; i < NBT * 32; i += TPB) {            // 1024
            float4 v = dx4[i];
            int bl = i >> 5, s0 = (i & 31) * 2;
            sgx[s0 * PSTR + bl]       = 2.f * v.x;
            sgy[s0 * PSTR + bl]       = 2.f * v.y;
            sgx[(s0 + 1) * PSTR + bl] = 2.f * v.z;
            sgy[(s0 + 1) * PSTR + bl] = 2.f * v.w;
        }
    }
    float v0v = (role == 0) ? v0[b0 + col] : 0.f;
    __syncthreads();

    // partition geometry: interiors {6,5,6,5,6,5,5,5} at {0,9,17,26,34,43,51,59}
    const int s = (role < 5 && !(role & 1)) ? 6 : 5;
    int hp = (role + 1) >> 1; if (hp > 3) hp = 3;
    const int o = role * 8 + hp;
    const bool hasL = (role > 0), hasR = (role < 7);
    const int ec = hasR ? (s + 3) : s;

    // ---- Phase 1: sincos -> e, rhs (registers) ----
    float earr[9], rarr[9];
    {
        float thp = sth[o * PSTR + col];
        float sp, cp; __sincosf(thp, &sp, &cp);
        float gxp = sgx[o * PSTR + col], gyp = sgy[o * PSTR + col];
        #pragma unroll
        for (int i = 1; i <= 9; ++i) {
            if (i <= ec) {
                int k = o + i;
                float th = sth[k * PSTR + col];
                float sv, cv; __sincosf(th, &sv, &cv);
                float gx = 0.f, gy = 0.f;
                if (k < 64) { gx = sgx[k * PSTR + col]; gy = sgy[k * PSTR + col]; }
                earr[i - 1] = cp * cv + sp * sv;
                rarr[i - 1] = cv * (gxp + gx) + sv * (gyp + gy);
                cp = cv; sp = sv; gxp = gx; gyp = gy;
            } else { earr[i - 1] = 0.f; rarr[i - 1] = 0.f; }
        }
        if (role == 0) {
            rarr[0] -= (earr[0] - 3.f * LAM3) * v0v;
            rarr[1] -= 3.f * LAM3 * v0v;
            rarr[2] += LAM3 * v0v;
        }
    }
    __syncthreads();   // phase-1 reads of sgx/sgy done; sgl alias now safe

    // runtime-s selects from register arrays
    const float e_s  = (s == 6) ? earr[6] : earr[5];
    const float e_s1 = (s == 6) ? earr[7] : earr[6];
    const float e_s2 = (s == 6) ? earr[8] : earr[7];
    const float r_s  = (s == 6) ? rarr[6] : rarr[5];
    const float r_s1 = (s == 6) ? rarr[7] : rarr[6];
    const float r_s2 = (s == 6) ? rarr[8] : rarr[7];

    // border coupling constants (from table, broadcast LDS)
    float aL0x=0,aL0y=0,aL0z=0, aL1y=0,aL1z=0, aL2z=0;
    if (hasL) {
        float4 cbm3 = sCb[o - 3];
        float4 cbm2 = sCb[o - 2];
        float4 cbm1 = sCb[o - 1];
        aL0x = cbm3.w;
        aL0y = cbm2.z;
        aL1y = cbm2.w;
        aL0z = earr[0] + cbm1.y;
        aL1z = cbm1.z;
        aL2z = cbm1.w;
    }
    float aR0x=0, aR1x=0,aR1y=0, aR2x=0,aR2y=0,aR2z=0;
    if (hasR) {
        int Je = o + s - 1;
        float4 cbe2 = sCb[Je - 2];
        float4 cbe1 = sCb[Je - 1];
        float4 cbe0 = sCb[Je];
        aR0x = cbe2.w;
        aR1x = cbe1.z;
        aR1y = cbe1.w;
        aR2x = e_s + cbe0.y;
        aR2y = cbe0.z;
        aR2z = cbe0.w;
    }

    // ---- Phase 2: bordered band Cholesky ----
    float L1p=0.f, L2p1=0.f, L2p2=0.f, L3p1=0.f, L3p2=0.f, L3p3=0.f;
    float zp1=0.f, zp2=0.f, zp3=0.f;
    float gl1x=0,gl1y=0,gl1z=0, gl2x=0,gl2y=0,gl2z=0, gl3x=0,gl3y=0,gl3z=0;
    float gr1x=0,gr1y=0,gr1z=0, gr2x=0,gr2y=0,gr2z=0, gr3x=0,gr3y=0,gr3z=0;
    float sl00=0,sl01=0,sl02=0,sl11=0,sl12=0,sl22=0;
    float sr00=0,sr01=0,sr02=0,sr11=0,sr12=0,sr22=0;
    float sx00=0,sx01=0,sx02=0,sx10=0,sx11=0,sx12=0,sx20=0,sx21=0,sx22=0;
    float rl0=0,rl1=0,rl2=0, rr0=0,rr1=0,rr2=0;

    #pragma unroll
    for (int jj = 0; jj < 6; ++jj) {
        if (jj < s) {
            int j = o + jj;
            float4 cb = sCb[j];          // broadcast, conflict-free
            float d   = cb.x - L1p*L1p - L2p2*L2p2 - L3p3*L3p3;
            float inv = rsqrtf(d);
            float s1v = (jj < s - 1)
                      ? (earr[jj + 1] + cb.y - L2p1*L1p - L3p2*L2p2) : 0.f;
            float s2v = (jj < s - 2) ? (cb.z - L3p1*L1p) : 0.f;
            float s3v = (jj < s - 3) ? cb.w : 0.f;
            float L1 = s1v * inv, L2 = s2v * inv, L3 = s3v * inv;
            float z  = (rarr[jj] - L1p*zp1 - L2p2*zp2 - L3p3*zp3) * inv;

            float4 pk;
            pk.x = L1 * inv; pk.y = L2 * inv; pk.z = L3 * inv; pk.w = z * inv;
            s4[(role * 6 + jj) * 32 + col] = pk;

            float glx=0, gly=0, glz=0;
            if (hasL) {
                float ax = (jj == 0) ? aL0x : 0.f;
                float ay = (jj == 0) ? aL0y : (jj == 1) ? aL1y : 0.f;
                float az = (jj == 0) ? aL0z : (jj == 1) ? aL1z : (jj == 2) ? aL2z : 0.f;
                glx = (ax - L1p*gl1x - L2p2*gl2x - L3p3*gl3x) * inv;
                gly = (ay - L1p*gl1y - L2p2*gl2y - L3p3*gl3y) * inv;
                glz = (az - L1p*gl1z - L2p2*gl2z - L3p3*gl3z) * inv;
                sl00 += glx*glx; sl01 += glx*gly; sl02 += glx*glz;
                sl11 += gly*gly; sl12 += gly*glz; sl22 += glz*glz;
                rl0 += glx*z; rl1 += gly*z; rl2 += glz*z;
                int gb = (((role - 1) * 6 + jj) * 3) * 32 + col;
                sgl[gb]      = glx * inv;
                sgl[gb + 32] = gly * inv;
                sgl[gb + 64] = glz * inv;
            }
            if (hasR && jj >= s - 3) {
                int rstep = jj - (s - 3);
                float ax = (rstep == 0) ? aR0x : (rstep == 1) ? aR1x : aR2x;
                float ay = (rstep == 1) ? aR1y : (rstep == 2) ? aR2y : 0.f;
                float az = (rstep == 2) ? aR2z : 0.f;
                float grx = (ax - L1p*gr1x - L2p2*gr2x - L3p3*gr3x) * inv;
                float gry = (ay - L1p*gr1y - L2p2*gr2y - L3p3*gr3y) * inv;
                float grz = (az - L1p*gr1z - L2p2*gr2z - L3p3*gr3z) * inv;
                sr00 += grx*grx; sr01 += grx*gry; sr02 += grx*grz;
                sr11 += gry*gry; sr12 += gry*grz; sr22 += grz*grz;
                rr0 += grx*z; rr1 += gry*z; rr2 += grz*z;
                if (hasL) {
                    sx00 += glx*grx; sx01 += glx*gry; sx02 += glx*grz;
                    sx10 += gly*grx; sx11 += gly*gry; sx12 += gly*grz;
                    sx20 += glz*grx; sx21 += glz*gry; sx22 += glz*grz;
                }
                int gb = ((role * 3 + rstep) * 3) * 32 + col;
                sgr[gb]      = grx * inv;
                sgr[gb + 32] = gry * inv;
                sgr[gb + 64] = grz * inv;
                gr3x=gr2x; gr3y=gr2y; gr3z=gr2z;
                gr2x=gr1x; gr2y=gr1y; gr2z=gr1z;
                gr1x=grx;  gr1y=gry;  gr1z=grz;
            }
            if (hasL) {
                gl3x=gl2x; gl3y=gl2y; gl3z=gl2z;
                gl2x=gl1x; gl2y=gl1y; gl2z=gl1z;
                gl1x=glx;  gl1y=gly;  gl1z=glz;
            }
            L3p3=L3p2; L3p2=L3p1; L3p1=L3;
            L2p2=L2p1; L2p1=L2; L1p=L1;
            zp3=zp2; zp2=zp1; zp1=z;
        }
    }

    // ---- exchange: Schur pieces + interface originals ----
    if (hasL) {
        int bsl = (role - 1) * 6;
        SXF(bsl+0)=sl00; SXF(bsl+1)=sl01; SXF(bsl+2)=sl02;
        SXF(bsl+3)=sl11; SXF(bsl+4)=sl12; SXF(bsl+5)=sl22;
        int brl = 138 + (role - 1) * 3;
        SXF(brl+0)=rl0; SXF(brl+1)=rl1; SXF(brl+2)=rl2;
    }
    if (hasR) {
        int bsr = 42 + role * 6;
        SXF(bsr+0)=sr00; SXF(bsr+1)=sr01; SXF(bsr+2)=sr02;
        SXF(bsr+3)=sr11; SXF(bsr+4)=sr12; SXF(bsr+5)=sr22;
        int brr = 159 + role * 3;
        SXF(brr+0)=rr0; SXF(brr+1)=rr1; SXF(brr+2)=rr2;
        int q = o + s;
        float4 tq0 = sCb[q];
        float4 tq1 = sCb[q + 1];
        float4 tq2 = sCb[q + 2];
        int bdd = 180 + role * 6;
        SXF(bdd+0) = tq0.x;
        SXF(bdd+1) = e_s1 + tq0.y;
        SXF(bdd+2) = tq0.z;
        SXF(bdd+3) = tq1.x;
        SXF(bdd+4) = e_s2 + tq1.y;
        SXF(bdd+5) = tq2.x;
        int brq = 222 + role * 3;
        SXF(brq+0)=r_s; SXF(brq+1)=r_s1; SXF(brq+2)=r_s2;
    }
    if (hasL && hasR) {
        int bcr = 84 + (role - 1) * 9;
        SXF(bcr+0)=sx00; SXF(bcr+1)=sx01; SXF(bcr+2)=sx02;
        SXF(bcr+3)=sx10; SXF(bcr+4)=sx11; SXF(bcr+5)=sx12;
        SXF(bcr+6)=sx20; SXF(bcr+7)=sx21; SXF(bcr+8)=sx22;
    }
    __syncthreads();

    // ---- interface: 7-block (3x3) block-tridiagonal solve, warp 0 only ----
    if (role == 0) {
        float fi0[7],fl10[7],fl20[7],fi1[7],fl21[7],fi2[7];
        float fu0[7],fu1[7],fu2[7];
        float W00a[7],W01a[7],W02a[7],W10a[7],W11a[7],W12a[7],W20a[7],W21a[7],W22a[7];
        #pragma unroll
        for (int i = 0; i < 7; ++i) {
            float D00 = SXF(180+i*6+0) - SXF(42+i*6+0) - SXF(i*6+0);
            float D10 = SXF(180+i*6+1) - SXF(42+i*6+1) - SXF(i*6+1);
            float D20 = SXF(180+i*6+2) - SXF(42+i*6+2) - SXF(i*6+2);
            float D11 = SXF(180+i*6+3) - SXF(42+i*6+3) - SXF(i*6+3);
            float D21 = SXF(180+i*6+4) - SXF(42+i*6+4) - SXF(i*6+4);
            float D22 = SXF(180+i*6+5) - SXF(42+i*6+5) - SXF(i*6+5);
            float t0  = SXF(222+i*3+0) - SXF(159+i*3+0) - SXF(138+i*3+0);
            float t1  = SXF(222+i*3+1) - SXF(159+i*3+1) - SXF(138+i*3+1);
            float t2  = SXF(222+i*3+2) - SXF(159+i*3+2) - SXF(138+i*3+2);
            if (i > 0) {
                int cb = 84 + (i - 1) * 9;
                float B00=-SXF(cb+0), B01=-SXF(cb+3), B02=-SXF(cb+6);
                float B10=-SXF(cb+1), B11=-SXF(cb+4), B12=-SXF(cb+7);
                float B20=-SXF(cb+2), B21=-SXF(cb+5), B22=-SXF(cb+8);
                FSOLVE(fi0[i-1],fl10[i-1],fl20[i-1],fi1[i-1],fl21[i-1],fi2[i-1],
                       B00,B01,B02, W00a[i],W01a[i],W02a[i])
                FSOLVE(fi0[i-1],fl10[i-1],fl20[i-1],fi1[i-1],fl21[i-1],fi2[i-1],
                       B10,B11,B12, W10a[i],W11a[i],W12a[i])
                FSOLVE(fi0[i-1],fl10[i-1],fl20[i-1],fi1[i-1],fl21[i-1],fi2[i-1],
                       B20,B21,B22, W20a[i],W21a[i],W22a[i])
                D00 -= W00a[i]*W00a[i] + W01a[i]*W01a[i] + W02a[i]*W02a[i];
                D10 -= W10a[i]*W00a[i] + W11a[i]*W01a[i] + W12a[i]*W02a[i];
                D20 -= W20a[i]*W00a[i] + W21a[i]*W01a[i] + W22a[i]*W02a[i];
                D11 -= W10a[i]*W10a[i] + W11a[i]*W11a[i] + W12a[i]*W12a[i];
                D21 -= W20a[i]*W10a[i] + W21a[i]*W11a[i] + W22a[i]*W12a[i];
                D22 -= W20a[i]*W20a[i] + W21a[i]*W21a[i] + W22a[i]*W22a[i];
                t0  -= W00a[i]*fu0[i-1] + W01a[i]*fu1[i-1] + W02a[i]*fu2[i-1];
                t1  -= W10a[i]*fu0[i-1] + W11a[i]*fu1[i-1] + W12a[i]*fu2[i-1];
                t2  -= W20a[i]*fu0[i-1] + W21a[i]*fu1[i-1] + W22a[i]*fu2[i-1];
            }
            fi0[i]  = rsqrtf(D00);
            fl10[i] = D10 * fi0[i];
            fl20[i] = D20 * fi0[i];
            fi1[i]  = rsqrtf(D11 - fl10[i]*fl10[i]);
            fl21[i] = (D21 - fl20[i]*fl10[i]) * fi1[i];
            fi2[i]  = rsqrtf(D22 - fl20[i]*fl20[i] - fl21[i]*fl21[i]);
            FSOLVE(fi0[i],fl10[i],fl20[i],fi1[i],fl21[i],fi2[i],
                   t0,t1,t2, fu0[i],fu1[i],fu2[i])
        }
        float xc0=0.f, xc1=0.f, xc2=0.f;
        #pragma unroll
        for (int i = 6; i >= 0; --i) {
            float t0 = fu0[i], t1 = fu1[i], t2 = fu2[i];
            if (i < 6) {
                t0 -= W00a[i+1]*xc0 + W10a[i+1]*xc1 + W20a[i+1]*xc2;
                t1 -= W01a[i+1]*xc0 + W11a[i+1]*xc1 + W21a[i+1]*xc2;
                t2 -= W02a[i+1]*xc0 + W12a[i+1]*xc1 + W22a[i+1]*xc2;
            }
            float x0, x1, x2;
            BSOLVE(fi0[i],fl10[i],fl20[i],fi1[i],fl21[i],fi2[i], t0,t1,t2, x0,x1,x2)
            SXF(243+i*3+0) = x0; SXF(243+i*3+1) = x1; SXF(243+i*3+2) = x2;
            xc0 = x0; xc1 = x1; xc2 = x2;
        }
    }
    __syncthreads();

    // ---- read interface solutions ----
    float xL0=0,xL1=0,xL2=0, xR0=0,xR1=0,xR2=0;
    if (hasL) {
        int xb = 243 + (role - 1) * 3;
        xL0 = SXF(xb+0); xL1 = SXF(xb+1); xL2 = SXF(xb+2);
    }
    if (hasR) {
        int xb = 243 + role * 3;
        xR0 = SXF(xb+0); xR1 = SXF(xb+1); xR2 = SXF(xb+2);
    }

    // ---- back substitution (interiors), stage output ----
    {
        float y1 = hasR ? xR0 : 0.f;
        float y2 = hasR ? xR1 : 0.f;
        float y3 = hasR ? xR2 : 0.f;
        #pragma unroll
        for (int jj = 5; jj >= 0; --jj) {
            if (jj < s) {
                float4 pk = s4[(role * 6 + jj) * 32 + col];
                float w = pk.w;
                if (hasL) {
                    int gb = (((role - 1) * 6 + jj) * 3) * 32 + col;
                    w -= sgl[gb] * xL0 + sgl[gb + 32] * xL1 + sgl[gb + 64] * xL2;
                }
                if (hasR && jj >= s - 3) {
                    int gb = ((role * 3 + (jj - (s - 3))) * 3) * 32 + col;
                    w -= sgr[gb] * xR0 + sgr[gb + 32] * xR1 + sgr[gb + 64] * xR2;
                }
                float x = w - pk.x * y1 - pk.y * y2 - pk.z * y3;
                sou[(o + jj + 1) * PSTR + col] = x;
                y3 = y2; y2 = y1; y1 = x;
            }
        }
        if (role == 0) sou[col] = v0v;
        if (hasR) {
            int q = o + s;
            sou[(q + 1) * PSTR + col] = xR0;
            sou[(q + 2) * PSTR + col] = xR1;
            sou[(q + 3) * PSTR + col] = xR2;
        }
    }
    __syncthreads();

    // ---- coalesced float4 store ----
    {
        float4* out4 = (float4*)(out + (size_t)b0 * NP);
        for (int i = t; i < (NBT * NP) / 4; i += TPB) {
            int f = 4 * i;
            int bl0 = f / NP, k0 = f - bl0 * NP;
            int f1 = f + 1, bl1 = f1 / NP, k1 = f1 - bl1 * NP;
            int f2 = f + 2, bl2 = f2 / NP, k2 = f2 - bl2 * NP;
            int f3 = f + 3, bl3 = f3 / NP, k3 = f3 - bl3 * NP;
            float4 v;
            v.x = sou[k0 * PSTR + bl0];
            v.y = sou[k1 * PSTR + bl1];
            v.z = sou[k2 * PSTR + bl2];
            v.w = sou[k3 * PSTR + bl3];
            out4[i] = v;
        }
    }
}

extern "C" void kernel_launch(void* const* d_in, const int* in_sizes, int n_in,
                              void* d_out, int out_size) {
    const float* dxy   = (const float*)d_in[0];
    const float* theta = (const float*)d_in[1];
    const float* v0    = (const float*)d_in[2];
    float* out = (float*)d_out;
    int B = in_sizes[2];

    cudaFuncSetAttribute(AlpamayoR1_solve_kernel,
                         cudaFuncAttributeMaxDynamicSharedMemorySize, SMEM_BYTES);
    int grid = (B + NBT - 1) / NBT;
    AlpamayoR1_solve_kernel<<<grid, TPB, SMEM_BYTES>>>(dxy, theta, v0, out, B);
}